// round 13
// baseline (speedup 1.0000x reference)
#include <cuda_runtime.h>
#include <cuda_fp16.h>
#include <cstdint>

// EnsKF step. fp16 3-term split mma GEMMs with IN-KERNEL fp32->hi/lo split
// (g_Ehi/g_Elo arrays and k_splitE deleted; E fp32 is same bytes as hi+lo).
// Cholesky: warp-factored diag blocks + parallel panel trsm via Dinv (k_invdiag folded in).
//   G  = E @ H;  Gc = G - colmean;  A = Gc^T Gc/ens + diag(std^2);  L = chol(A)
//   Z  = A^{-1} innov;  W' = I + (1/ens)(Gc @ Z)^T -> fp16 hi/lo;  out = W' @ E

#define BATCH 8
#define ENSN  256
#define XDIM  8192
#define NSQ   65536
#define SPLITS 8

__device__ __align__(256) float g_part[SPLITS * BATCH * NSQ];
__device__ __align__(256) float g_G[BATCH * NSQ];
__device__ __align__(256) float g_mu[BATCH * 256];
__device__ __align__(256) float g_A[BATCH * NSQ];
__device__ __align__(256) float g_Z[BATCH * NSQ];
__device__ __align__(256) float g_Dinv[BATCH * 8 * 32 * 32];
__device__ __align__(256) __half g_Hhi[XDIM * 256];
__device__ __align__(256) __half g_Hlo[XDIM * 256];
__device__ __align__(256) __half g_Whi[BATCH * NSQ];
__device__ __align__(256) __half g_Wlo[BATCH * NSQ];

// ---------------- low-level helpers ----------------
__device__ __forceinline__ uint32_t smem_u32(const void* p) {
    uint32_t a;
    asm("{ .reg .u64 t; cvta.to.shared.u64 t, %1; cvt.u32.u64 %0, t; }" : "=r"(a) : "l"(p));
    return a;
}
__device__ __forceinline__ void cpa16(uint32_t dst, const void* src) {
    asm volatile("cp.async.cg.shared.global [%0], [%1], 16;" :: "r"(dst), "l"(src));
}
#define CPC() asm volatile("cp.async.commit_group;" ::: "memory")
#define CPW1() asm volatile("cp.async.wait_group 1;" ::: "memory")
__device__ __forceinline__ void ldsm4(uint32_t* r, uint32_t a) {
    asm volatile("ldmatrix.sync.aligned.m8n8.x4.shared.b16 {%0,%1,%2,%3}, [%4];"
                 : "=r"(r[0]), "=r"(r[1]), "=r"(r[2]), "=r"(r[3]) : "r"(a));
}
__device__ __forceinline__ void ldsm4t(uint32_t* r, uint32_t a) {
    asm volatile("ldmatrix.sync.aligned.m8n8.x4.trans.shared.b16 {%0,%1,%2,%3}, [%4];"
                 : "=r"(r[0]), "=r"(r[1]), "=r"(r[2]), "=r"(r[3]) : "r"(a));
}
__device__ __forceinline__ void mma16816(float* c, const uint32_t* a, const uint32_t* b) {
    asm volatile("mma.sync.aligned.m16n8k16.row.col.f32.f16.f16.f32 "
                 "{%0,%1,%2,%3},{%4,%5,%6,%7},{%8,%9},{%0,%1,%2,%3};"
                 : "+f"(c[0]), "+f"(c[1]), "+f"(c[2]), "+f"(c[3])
                 : "r"(a[0]), "r"(a[1]), "r"(a[2]), "r"(a[3]), "r"(b[0]), "r"(b[1]));
}
__device__ __forceinline__ uint32_t packh2(__half a, __half b) {
    __half2 t = __halves2half2(a, b);
    return *reinterpret_cast<uint32_t*>(&t);
}
__device__ __forceinline__ void lds128(float4& f, uint32_t a) {
    asm volatile("ld.shared.v4.f32 {%0,%1,%2,%3}, [%4];"
                 : "=f"(f.x), "=f"(f.y), "=f"(f.z), "=f"(f.w) : "r"(a));
}
__device__ __forceinline__ void sts64(uint32_t a, uint32_t v0, uint32_t v1) {
    asm volatile("st.shared.v2.u32 [%0], {%1,%2};" :: "r"(a), "r"(v0), "r"(v1) : "memory");
}
// convert one float4 -> hi/lo half2 pairs at smem addrs
__device__ __forceinline__ void cvt_hilo(uint32_t hiA, uint32_t loA, float4 f) {
    __half hx = __float2half_rn(f.x), hy = __float2half_rn(f.y);
    __half hz = __float2half_rn(f.z), hw = __float2half_rn(f.w);
    __half lx = __float2half_rn(f.x - __half2float(hx));
    __half ly = __float2half_rn(f.y - __half2float(hy));
    __half lz = __float2half_rn(f.z - __half2float(hz));
    __half lw = __float2half_rn(f.w - __half2float(hw));
    sts64(hiA, packh2(hx, hy), packh2(hz, hw));
    sts64(loA, packh2(lx, ly), packh2(lz, lw));
}

// ---------------- shared warp compute: one 32-K chunk, 3-term split ----------------
__device__ __forceinline__ void compute_chunk(uint32_t aHi, uint32_t aLo,
                                              uint32_t bHi, uint32_t bLo,
                                              int lane, int wm, int wn,
                                              float acc[4][4][4]) {
    const int arow = lane & 15, aoff = (lane >> 4) * 16;
    const int brow = (lane & 7) + ((lane >> 3) & 1) * 8, boff = (lane >> 4) * 16;
#pragma unroll
    for (int k16 = 0; k16 < 2; k16++) {
        uint32_t bh[2][4], bl[2][4];
#pragma unroll
        for (int nj = 0; nj < 2; nj++) {
            ldsm4t(bh[nj], bHi + (k16 * 16 + brow) * 272 + (wn + nj * 16) * 2 + boff);
            ldsm4t(bl[nj], bLo + (k16 * 16 + brow) * 272 + (wn + nj * 16) * 2 + boff);
        }
#pragma unroll
        for (int mi = 0; mi < 4; mi++) {
            uint32_t ah[4], al[4];
            ldsm4(ah, aHi + (wm + 16 * mi + arow) * 80 + k16 * 32 + aoff);
            ldsm4(al, aLo + (wm + 16 * mi + arow) * 80 + k16 * 32 + aoff);
#pragma unroll
            for (int n8 = 0; n8 < 4; n8++)
                mma16816(acc[mi][n8], ah, &bh[n8 >> 1][(n8 & 1) * 2]);
#pragma unroll
            for (int n8 = 0; n8 < 4; n8++)
                mma16816(acc[mi][n8], ah, &bl[n8 >> 1][(n8 & 1) * 2]);
#pragma unroll
            for (int n8 = 0; n8 < 4; n8++)
                mma16816(acc[mi][n8], al, &bh[n8 >> 1][(n8 & 1) * 2]);
        }
    }
}

// ===========================================================================
// GEMM1: split-K partials of G = E @ H; A operand (E fp32) converted in-kernel.
// smem: staging 128x144B (18432) | Asplit 2hl x 10240 | Bsplit 2buf x 2hl x 8704
// ===========================================================================
#define M1_STG 0
#define M1_A0  18432
#define M1_B0  38912
#define GSMEM1 73728

__global__ __launch_bounds__(256, 2) void k_mm1(const float* __restrict__ E) {
    extern __shared__ char smem[];
    const uint32_t sb = smem_u32(smem);
    const int mt = blockIdx.x >> 1, nt = blockIdx.x & 1;
    const int s = blockIdx.y, b = blockIdx.z;
    const int tid = threadIdx.x, lane = tid & 31, w = tid >> 5;
    const int wm = (w & 1) * 64, wn = (w >> 1) * 32;
    const float* Af = E + ((size_t)b * ENSN + mt * 128) * XDIM + (size_t)s * 1024;
    const __half* Bh = g_Hhi + (size_t)(s * 1024) * 256 + nt * 128;
    const __half* Bl = g_Hlo + (size_t)(s * 1024) * 256 + nt * 128;

    float acc[4][4][4];
#pragma unroll
    for (int i = 0; i < 4; i++)
#pragma unroll
        for (int j = 0; j < 4; j++)
#pragma unroll
            for (int q = 0; q < 4; q++) acc[i][j][q] = 0.0f;

    // producers
    auto issA = [&](int kbase) {
#pragma unroll
        for (int it = 0; it < 4; it++) {
            const int i = tid + it * 256;
            const int r = i >> 3, seg = i & 7;
            cpa16(sb + M1_STG + r * 144 + seg * 16, Af + (size_t)r * XDIM + kbase + seg * 4);
        }
    };
    auto issB = [&](int buf, int kbase) {
#pragma unroll
        for (int hl = 0; hl < 2; hl++) {
            const __half* src = hl ? Bl : Bh;
#pragma unroll
            for (int it = 0; it < 2; it++) {
                const int i = tid + it * 256;
                const int r = i >> 4, seg = i & 15;
                cpa16(sb + M1_B0 + buf * 17408 + hl * 8704 + r * 272 + seg * 16,
                      src + (size_t)(kbase + r) * 256 + seg * 8);
            }
        }
    };

    issA(0); issB(0, 0); CPC();
    issB(1, 32); CPC();

    const int r2 = tid >> 1, h2 = tid & 1;
    for (int c = 0; c < 32; c++) {
        CPW1();
        __syncthreads();
        // convert staging -> A split tiles
#pragma unroll
        for (int q = 0; q < 4; q++) {
            float4 f;
            lds128(f, sb + M1_STG + r2 * 144 + h2 * 64 + q * 16);
            cvt_hilo(sb + M1_A0 + r2 * 80 + h2 * 32 + q * 8,
                     sb + M1_A0 + 10240 + r2 * 80 + h2 * 32 + q * 8, f);
        }
        __syncthreads();
        if (c + 1 < 32) issA((c + 1) * 32);
        CPC();
        compute_chunk(sb + M1_A0, sb + M1_A0 + 10240,
                      sb + M1_B0 + (c & 1) * 17408, sb + M1_B0 + (c & 1) * 17408 + 8704,
                      lane, wm, wn, acc);
        __syncthreads();
        if (c + 2 < 32) issB(c & 1, (c + 2) * 32);
        CPC();
    }

    float* Cp = g_part + (size_t)(s * BATCH + b) * NSQ + (mt * 128) * 256 + nt * 128;
#pragma unroll
    for (int mi = 0; mi < 4; mi++)
#pragma unroll
        for (int n8 = 0; n8 < 4; n8++) {
            const int r = wm + 16 * mi + (lane >> 2);
            const int cc = wn + n8 * 8 + (lane & 3) * 2;
            *(float2*)(Cp + r * 256 + cc) = make_float2(acc[mi][n8][0], acc[mi][n8][1]);
            *(float2*)(Cp + (r + 8) * 256 + cc) = make_float2(acc[mi][n8][2], acc[mi][n8][3]);
        }
}

// ===========================================================================
// GEMM3: out = W' @ E; B operand (E fp32) converted in-kernel.
// smem: staging 32x544B (17408) | Asplit 2buf x 2hl x 10240 | Bsplit 2hl x 8704
// ===========================================================================
#define M3_STG 0
#define M3_A0  17408
#define M3_B0  58368
#define GSMEM3 75776

__global__ __launch_bounds__(256, 2) void k_mm3(const float* __restrict__ E,
                                                float* __restrict__ out) {
    extern __shared__ char smem[];
    const uint32_t sb = smem_u32(smem);
    const int nt = blockIdx.x, mt = blockIdx.y, b = blockIdx.z;
    const int n0 = nt * 128;
    const int tid = threadIdx.x, lane = tid & 31, w = tid >> 5;
    const int wm = (w & 1) * 64, wn = (w >> 1) * 32;
    const float* Bf = E + (size_t)b * ENSN * XDIM + n0;
    const __half* Ah = g_Whi + (size_t)b * NSQ + (size_t)(mt * 128) * 256;
    const __half* Al = g_Wlo + (size_t)b * NSQ + (size_t)(mt * 128) * 256;

    float acc[4][4][4];
#pragma unroll
    for (int i = 0; i < 4; i++)
#pragma unroll
        for (int j = 0; j < 4; j++)
#pragma unroll
            for (int q = 0; q < 4; q++) acc[i][j][q] = 0.0f;

    auto issB = [&](int kbase) {
#pragma unroll
        for (int it = 0; it < 4; it++) {
            const int i = tid + it * 256;
            const int k = i >> 5, seg = i & 31;
            cpa16(sb + M3_STG + k * 544 + seg * 16,
                  Bf + (size_t)(kbase + k) * XDIM + seg * 4);
        }
    };
    auto issA = [&](int buf, int kbase) {
#pragma unroll
        for (int hl = 0; hl < 2; hl++) {
            const __half* src = hl ? Al : Ah;
#pragma unroll
            for (int it = 0; it < 2; it++) {
                const int i = tid + it * 256;
                const int r = i >> 2, seg = i & 3;
                cpa16(sb + M3_A0 + buf * 20480 + hl * 10240 + r * 80 + seg * 16,
                      src + (size_t)r * 256 + kbase + seg * 8);
            }
        }
    };

    issB(0); issA(0, 0); CPC();
    issA(1, 32); CPC();

    const int k8 = tid >> 3, s8 = tid & 7;
    for (int c = 0; c < 8; c++) {
        CPW1();
        __syncthreads();
#pragma unroll
        for (int q = 0; q < 4; q++) {
            float4 f;
            lds128(f, sb + M3_STG + k8 * 544 + s8 * 64 + q * 16);
            cvt_hilo(sb + M3_B0 + k8 * 272 + s8 * 32 + q * 8,
                     sb + M3_B0 + 8704 + k8 * 272 + s8 * 32 + q * 8, f);
        }
        __syncthreads();
        if (c + 1 < 8) issB((c + 1) * 32);
        CPC();
        compute_chunk(sb + M3_A0 + (c & 1) * 20480, sb + M3_A0 + (c & 1) * 20480 + 10240,
                      sb + M3_B0, sb + M3_B0 + 8704,
                      lane, wm, wn, acc);
        __syncthreads();
        if (c + 2 < 8) issA(c & 1, (c + 2) * 32);
        CPC();
    }

    float* Op = out + (size_t)b * ENSN * XDIM;
#pragma unroll
    for (int mi = 0; mi < 4; mi++)
#pragma unroll
        for (int n8 = 0; n8 < 4; n8++) {
            const int e = mt * 128 + wm + 16 * mi + (lane >> 2);
            const int x = n0 + wn + n8 * 8 + (lane & 3) * 2;
            *(float2*)(Op + (size_t)e * XDIM + x) =
                make_float2(acc[mi][n8][0], acc[mi][n8][1]);
            *(float2*)(Op + (size_t)(e + 8) * XDIM + x) =
                make_float2(acc[mi][n8][2], acc[mi][n8][3]);
        }
}

// ---------------------------------------------------------------------------
__global__ void k_dummy() {
    const int i = threadIdx.x;
#pragma unroll
    for (int r = 0; r < 8; r++) g_mu[r * 256 + i] = 0.0f;
}

__global__ __launch_bounds__(256) void k_splitH(const float* __restrict__ H) {
    const size_t i = (size_t)blockIdx.x * 256 + threadIdx.x;
    float4 v = ((const float4*)H)[i];
    __half hx = __float2half_rn(v.x), hy = __float2half_rn(v.y);
    __half hz = __float2half_rn(v.z), hw = __float2half_rn(v.w);
    __half2* hi = (__half2*)g_Hhi;
    __half2* lo = (__half2*)g_Hlo;
    hi[2 * i]     = __halves2half2(hx, hy);
    hi[2 * i + 1] = __halves2half2(hz, hw);
    lo[2 * i]     = __halves2half2(__float2half_rn(v.x - __half2float(hx)),
                                   __float2half_rn(v.y - __half2float(hy)));
    lo[2 * i + 1] = __halves2half2(__float2half_rn(v.z - __half2float(hz)),
                                   __float2half_rn(v.w - __half2float(hw)));
}

__global__ __launch_bounds__(256) void k_reduce() {
    const int i = blockIdx.x * 256 + threadIdx.x;
    const float4* P = (const float4*)g_part;
    float4 s = P[i];
#pragma unroll
    for (int p = 1; p < SPLITS; p++) {
        float4 v = P[(size_t)p * (BATCH * NSQ / 4) + i];
        s.x += v.x; s.y += v.y; s.z += v.z; s.w += v.w;
    }
    ((float4*)g_G)[i] = s;
}

__global__ __launch_bounds__(256) void k_colmean() {
    const int b = blockIdx.y;
    const int j = blockIdx.x * 32 + (threadIdx.x & 31);
    const int er = threadIdx.x >> 5;
    const float* G = g_G + b * NSQ;
    float s = 0.0f;
    for (int e = er; e < ENSN; e += 8) s += G[e * 256 + j];
    __shared__ float red[8][32];
    red[er][threadIdx.x & 31] = s;
    __syncthreads();
    if (er == 0) {
        float t = 0.0f;
#pragma unroll
        for (int r = 0; r < 8; r++) t += red[r][threadIdx.x & 31];
        g_mu[b * 256 + j] = t * (1.0f / 256.0f);
    }
}

__global__ __launch_bounds__(256) void k_centerT(const float* __restrict__ ymean,
                                                 const float* __restrict__ ystd,
                                                 const float* __restrict__ noise) {
    const int b = blockIdx.z, j0 = blockIdx.y * 32, e0 = blockIdx.x * 32;
    float* G = g_G + b * NSQ;
    float* Z = g_Z + b * NSQ;
    const float* nz = noise + b * NSQ;
    __shared__ float T[32][33];
    const int tx = threadIdx.x & 31, ty = threadIdx.x >> 5;
    const float mu = g_mu[b * 256 + j0 + tx];
#pragma unroll
    for (int r = 0; r < 4; r++) {
        const int e = e0 + ty + r * 8;
        float gc = G[e * 256 + j0 + tx] - mu;
        G[e * 256 + j0 + tx] = gc;
        T[ty + r * 8][tx] = gc;
    }
    __syncthreads();
#pragma unroll
    for (int r = 0; r < 4; r++) {
        const int j = j0 + ty + r * 8;
        const float ym = ymean[j];
        const float sd = ystd[j];
        Z[j * 256 + e0 + tx] = ym - T[tx][ty + r * 8] + nz[j * 256 + e0 + tx] * sd * sd;
    }
}

__global__ __launch_bounds__(256) void k_cyy(const float* __restrict__ ystd) {
    const int b = blockIdx.y;
    const int u0 = (blockIdx.x >> 2) * 64, v0 = (blockIdx.x & 3) * 64;
    const float* G = g_G + b * NSQ;
    float* A = g_A + b * NSQ;
    __shared__ float Us[16][64];
    __shared__ float Vs[16][64];
    const int tx = threadIdx.x & 15, ty = threadIdx.x >> 4;
    const int lk = threadIdx.x >> 4, lc = (threadIdx.x & 15) * 4;
    float acc[4][4];
#pragma unroll
    for (int i = 0; i < 4; i++)
#pragma unroll
        for (int j = 0; j < 4; j++) acc[i][j] = 0.0f;

    for (int ee = 0; ee < 256; ee += 16) {
        *(float4*)&Us[lk][lc] = *(const float4*)&G[(ee + lk) * 256 + u0 + lc];
        *(float4*)&Vs[lk][lc] = *(const float4*)&G[(ee + lk) * 256 + v0 + lc];
        __syncthreads();
#pragma unroll
        for (int k = 0; k < 16; k++) {
            float4 u = *(float4*)&Us[k][ty * 4];
            float4 v = *(float4*)&Vs[k][tx * 4];
            float ua[4] = {u.x, u.y, u.z, u.w};
            float va[4] = {v.x, v.y, v.z, v.w};
#pragma unroll
            for (int i = 0; i < 4; i++)
#pragma unroll
                for (int j = 0; j < 4; j++) acc[i][j] = fmaf(ua[i], va[j], acc[i][j]);
        }
        __syncthreads();
    }
#pragma unroll
    for (int i = 0; i < 4; i++)
#pragma unroll
        for (int j = 0; j < 4; j++) {
            const int u = u0 + ty * 4 + i, v = v0 + tx * 4 + j;
            float val = acc[i][j] * (1.0f / 256.0f);
            if (u == v) { float sd = ystd[u]; val += sd * sd; }
            A[u * 256 + v] = val;
        }
}

// ---------------------------------------------------------------------------
// Cholesky: warp-factored 32x32 diag blocks + Dinv (to g_Dinv) + parallel
// panel trsm (L_panel = A_panel * Dinv^T) + 4x4 reg-tiled trailing update.
// grid(8 = batch), 256 threads.
// ---------------------------------------------------------------------------
__global__ __launch_bounds__(256) void k_chol() {
    const int b = blockIdx.x;
    float* a = g_A + b * NSQ;
    __shared__ float Ds[32][33];
    __shared__ float Dv[32][36];
    __shared__ float P[224][33];
    const int tid = threadIdx.x, lane = tid & 31;

    for (int kb = 0; kb < 8; kb++) {
        const int j0 = kb * 32;
        const int rem = 224 - j0;
        // load diag block
#pragma unroll
        for (int q = 0; q < 4; q++) {
            const int idx = tid + q * 256;
            Ds[idx >> 5][idx & 31] = a[(j0 + (idx >> 5)) * 256 + j0 + (idx & 31)];
        }
        __syncthreads();
        // warp 0: factorize diag block (lower)
        if (tid < 32) {
            for (int k = 0; k < 32; k++) {
                const float piv = Ds[k][k];
                const float d = sqrtf(piv);
                const float rd = 1.0f / d;
                if (lane == k) Ds[k][k] = d;
                float v = 0.0f;
                if (lane > k) { v = Ds[lane][k] * rd; Ds[lane][k] = v; }
                __syncwarp();
                if (lane > k)
                    for (int c = k + 1; c <= lane; c++) Ds[lane][c] -= v * Ds[c][k];
                __syncwarp();
            }
        }
        __syncthreads();
        // prefetch A panel row (all threads with a row) while warp0 builds Dinv
        float ar[32];
        if (tid < rem) {
            const int row = j0 + 32 + tid;
#pragma unroll
            for (int q = 0; q < 8; q++) {
                float4 v = *(const float4*)&a[row * 256 + j0 + q * 4];
                ar[q * 4 + 0] = v.x; ar[q * 4 + 1] = v.y;
                ar[q * 4 + 2] = v.z; ar[q * 4 + 3] = v.w;
            }
        }
        if (tid < 32) {
            // Dinv (column = lane, forward substitution)
            for (int i = 0; i < 32; i++) {
                float s = (i == lane) ? 1.0f : 0.0f;
                for (int k = lane; k < i; k++) s -= Ds[i][k] * Dv[k][lane];
                Dv[i][lane] = (i >= lane) ? s / Ds[i][i] : 0.0f;
            }
            for (int i = 0; i < 32; i++) {
                g_Dinv[(b * 8 + kb) * 1024 + i * 32 + lane] = Dv[i][lane];
                a[(j0 + i) * 256 + j0 + lane] = Ds[i][lane];
            }
        }
        __syncthreads();
        // panel trsm: L[r][c] = sum_k ar[k] * Dinv[c][k]
        if (tid < rem) {
            const int row = j0 + 32 + tid;
#pragma unroll
            for (int c4 = 0; c4 < 8; c4++) {
                float s[4] = {0.0f, 0.0f, 0.0f, 0.0f};
#pragma unroll
                for (int i = 0; i < 4; i++) {
                    const int c = c4 * 4 + i;
#pragma unroll
                    for (int q = 0; q < 8; q++) {
                        float4 dv = *(float4*)&Dv[c][q * 4];
                        s[i] = fmaf(ar[q * 4 + 0], dv.x, s[i]);
                        s[i] = fmaf(ar[q * 4 + 1], dv.y, s[i]);
                        s[i] = fmaf(ar[q * 4 + 2], dv.z, s[i]);
                        s[i] = fmaf(ar[q * 4 + 3], dv.w, s[i]);
                    }
                    P[tid][c] = s[i];
                }
                *(float4*)&a[row * 256 + j0 + c4 * 4] = make_float4(s[0], s[1], s[2], s[3]);
            }
        }
        __syncthreads();
        // trailing update
        if (rem > 0) {
            const int nt4 = rem >> 2;
            for (int t = tid; t < nt4 * nt4; t += 256) {
                const int ti = t / nt4, tj = t - ti * nt4;
                const int r0 = j0 + 32 + ti * 4, c0 = j0 + 32 + tj * 4;
                float4 acc[4];
#pragma unroll
                for (int i = 0; i < 4; i++)
                    acc[i] = *(float4*)&a[(r0 + i) * 256 + c0];
#pragma unroll
                for (int k = 0; k < 32; k++) {
                    float pr[4], pc[4];
#pragma unroll
                    for (int i = 0; i < 4; i++) {
                        pr[i] = P[ti * 4 + i][k];
                        pc[i] = P[tj * 4 + i][k];
                    }
#pragma unroll
                    for (int i = 0; i < 4; i++) {
                        acc[i].x = fmaf(-pr[i], pc[0], acc[i].x);
                        acc[i].y = fmaf(-pr[i], pc[1], acc[i].y);
                        acc[i].z = fmaf(-pr[i], pc[2], acc[i].z);
                        acc[i].w = fmaf(-pr[i], pc[3], acc[i].w);
                    }
                }
#pragma unroll
                for (int i = 0; i < 4; i++)
                    *(float4*)&a[(r0 + i) * 256 + c0] = acc[i];
            }
        }
        __syncthreads();
    }
}

// ---------------------------------------------------------------------------
// Trisolve, register-cached Z panel
// ---------------------------------------------------------------------------
#define TS_SMEM 129920
__global__ __launch_bounds__(256) void k_trisolve2() {
    extern __shared__ float sm[];
    float (*Zs)[65] = (float(*)[65])sm;
    float (*Dv)[33] = (float(*)[33])(sm + 256 * 65);
    float (*Lp)[33] = (float(*)[33])(sm + 256 * 65 + 256 * 33);
    const int b = blockIdx.y, e0 = blockIdx.x * 64;
    const float* L = g_A + b * NSQ;
    float* Z = g_Z + b * NSQ;
    const int tid = threadIdx.x, c = tid & 63, rg = tid >> 6;

    for (int idx = tid; idx < 256 * 64; idx += 256)
        Zs[idx >> 6][idx & 63] = Z[(idx >> 6) * 256 + e0 + (idx & 63)];
    for (int idx = tid; idx < 8 * 32 * 32; idx += 256)
        Dv[idx >> 5][idx & 31] = g_Dinv[b * 8192 + idx];
    __syncthreads();

    for (int p = 0; p < 8; p++) {
        const int j0 = p * 32, rem = 224 - j0;
        float zr[32];
#pragma unroll
        for (int k = 0; k < 32; k++) zr[k] = Zs[j0 + k][c];
        float w[8];
#pragma unroll
        for (int q = 0; q < 8; q++) {
            const int r = rg * 8 + q;
            float s = 0.0f;
#pragma unroll
            for (int k = 0; k < 32; k++) s = fmaf(Dv[p * 32 + r][k], zr[k], s);
            w[q] = s;
        }
        for (int idx = tid; idx < rem * 32; idx += 256)
            Lp[idx >> 5][idx & 31] = L[(j0 + 32 + (idx >> 5)) * 256 + j0 + (idx & 31)];
        __syncthreads();
#pragma unroll
        for (int q = 0; q < 8; q++) Zs[j0 + rg * 8 + q][c] = w[q];
        __syncthreads();
#pragma unroll
        for (int k = 0; k < 32; k++) zr[k] = Zs[j0 + k][c];
        for (int rr = rg; rr < rem; rr += 4) {
            float acc = Zs[j0 + 32 + rr][c];
#pragma unroll
            for (int k = 0; k < 32; k++) acc = fmaf(-Lp[rr][k], zr[k], acc);
            Zs[j0 + 32 + rr][c] = acc;
        }
        __syncthreads();
    }

    for (int p = 7; p >= 0; p--) {
        const int j0 = p * 32;
        float zr[32];
#pragma unroll
        for (int i = 0; i < 32; i++) zr[i] = Zs[j0 + i][c];
        float w[8];
#pragma unroll
        for (int q = 0; q < 8; q++) {
            const int k = rg * 8 + q;
            float s = 0.0f;
#pragma unroll
            for (int i = 0; i < 32; i++) s = fmaf(Dv[p * 32 + i][k], zr[i], s);
            w[q] = s;
        }
        for (int idx = tid; idx < j0 * 32; idx += 256)
            Lp[idx >> 5][idx & 31] = L[(j0 + (idx & 31)) * 256 + (idx >> 5)];
        __syncthreads();
#pragma unroll
        for (int q = 0; q < 8; q++) Zs[j0 + rg * 8 + q][c] = w[q];
        __syncthreads();
#pragma unroll
        for (int k = 0; k < 32; k++) zr[k] = Zs[j0 + k][c];
        for (int t = rg; t < j0; t += 4) {
            float acc = Zs[t][c];
#pragma unroll
            for (int k = 0; k < 32; k++) acc = fmaf(-Lp[t][k], zr[k], acc);
            Zs[t][c] = acc;
        }
        __syncthreads();
    }

    for (int idx = tid; idx < 256 * 64; idx += 256)
        Z[(idx >> 6) * 256 + e0 + (idx & 63)] = Zs[idx >> 6][idx & 63];
}

// W'[e][f] = (e==f) + (1/ens) sum_j Z[j][e] * Gc[f][j]  -> fp16 hi/lo
__global__ __launch_bounds__(256) void k_wp() {
    const int b = blockIdx.y;
    const int e0 = (blockIdx.x >> 2) * 64, f0 = (blockIdx.x & 3) * 64;
    const float* G = g_G + b * NSQ;
    const float* Z = g_Z + b * NSQ;
    __shared__ float sZ[16][64];
    __shared__ float sG[16][64];
    const int tx = threadIdx.x & 15, ty = threadIdx.x >> 4;
    const int lk = threadIdx.x >> 4, lc = (threadIdx.x & 15) * 4;
    const int gn = threadIdx.x >> 2, gk = (threadIdx.x & 3) * 4;
    float acc[4][4];
#pragma unroll
    for (int i = 0; i < 4; i++)
#pragma unroll
        for (int j = 0; j < 4; j++) acc[i][j] = 0.0f;

    for (int jj = 0; jj < 256; jj += 16) {
        *(float4*)&sZ[lk][lc] = *(const float4*)&Z[(jj + lk) * 256 + e0 + lc];
        float4 gv = *(const float4*)&G[(f0 + gn) * 256 + jj + gk];
        sG[gk + 0][gn] = gv.x; sG[gk + 1][gn] = gv.y;
        sG[gk + 2][gn] = gv.z; sG[gk + 3][gn] = gv.w;
        __syncthreads();
#pragma unroll
        for (int k = 0; k < 16; k++) {
            float4 zv = *(float4*)&sZ[k][ty * 4];
            float4 gg = *(float4*)&sG[k][tx * 4];
            float za[4] = {zv.x, zv.y, zv.z, zv.w};
            float ga[4] = {gg.x, gg.y, gg.z, gg.w};
#pragma unroll
            for (int i = 0; i < 4; i++)
#pragma unroll
                for (int j = 0; j < 4; j++) acc[i][j] = fmaf(za[i], ga[j], acc[i][j]);
        }
        __syncthreads();
    }
#pragma unroll
    for (int i = 0; i < 4; i++)
#pragma unroll
        for (int j = 0; j < 4; j++) {
            const int e = e0 + ty * 4 + i, f = f0 + tx * 4 + j;
            float val = acc[i][j] * (1.0f / 256.0f);
            if (e == f) val += 1.0f;
            __half h = __float2half_rn(val);
            g_Whi[b * NSQ + e * 256 + f] = h;
            g_Wlo[b * NSQ + e * 256 + f] = __float2half_rn(val - __half2float(h));
        }
}

// ---------------------------------------------------------------------------
extern "C" void kernel_launch(void* const* d_in, const int* in_sizes, int n_in,
                              void* d_out, int out_size) {
    const float* E     = (const float*)d_in[0];
    const float* H     = (const float*)d_in[1];
    const float* ymean = (const float*)d_in[2];
    const float* ystd  = (const float*)d_in[3];
    const float* noise = (const float*)d_in[4];
    float* out = (float*)d_out;

    cudaFuncSetAttribute(k_mm1, cudaFuncAttributeMaxDynamicSharedMemorySize, GSMEM1);
    cudaFuncSetAttribute(k_mm3, cudaFuncAttributeMaxDynamicSharedMemorySize, GSMEM3);
    cudaFuncSetAttribute(k_trisolve2, cudaFuncAttributeMaxDynamicSharedMemorySize, TS_SMEM);

    k_dummy<<<1, 256>>>();                                  // idx 0
    k_splitH<<<2048, 256>>>(H);                             // idx 1
    k_dummy<<<1, 256>>>();                                  // idx 2
    k_mm1<<<dim3(4, SPLITS, BATCH), 256, GSMEM1>>>(E);      // idx 3  <- ncu capture
    k_reduce<<<(BATCH * NSQ / 4) / 256, 256>>>();
    k_colmean<<<dim3(8, BATCH), 256>>>();
    k_centerT<<<dim3(8, 8, BATCH), 256>>>(ymean, ystd, noise);
    k_cyy<<<dim3(16, BATCH), 256>>>(ystd);
    k_chol<<<BATCH, 256>>>();
    k_trisolve2<<<dim3(4, BATCH), 256, TS_SMEM>>>();
    k_wp<<<dim3(16, BATCH), 256>>>();
    k_mm3<<<dim3(64, 2, BATCH), 256, GSMEM3>>>(E, out);
}

// round 14
// speedup vs baseline: 1.2256x; 1.2256x over previous
#include <cuda_runtime.h>
#include <cuda_fp16.h>
#include <cstdint>

// EnsKF step. fp16 3-term split mma GEMMs with in-kernel fp32->hi/lo split of E
// (no g_Ehi/g_Elo arrays, no splitE pass). Chol = parallel-pivot + reg-tiled
// trailing (r12); separate k_invdiag; reg-cached trisolve.
//   G  = E @ H;  Gc = G - colmean;  A = Gc^T Gc/ens + diag(std^2);  L = chol(A)
//   Z  = A^{-1} innov;  W' = I + (1/ens)(Gc @ Z)^T -> fp16 hi/lo;  out = W' @ E

#define BATCH 8
#define ENSN  256
#define XDIM  8192
#define NSQ   65536
#define SPLITS 8

__device__ __align__(256) float g_part[SPLITS * BATCH * NSQ];
__device__ __align__(256) float g_G[BATCH * NSQ];
__device__ __align__(256) float g_mu[BATCH * 256];
__device__ __align__(256) float g_A[BATCH * NSQ];
__device__ __align__(256) float g_Z[BATCH * NSQ];
__device__ __align__(256) float g_Dinv[BATCH * 8 * 32 * 32];
__device__ __align__(256) __half g_Hhi[XDIM * 256];
__device__ __align__(256) __half g_Hlo[XDIM * 256];
__device__ __align__(256) __half g_Whi[BATCH * NSQ];
__device__ __align__(256) __half g_Wlo[BATCH * NSQ];

// ---------------- low-level helpers ----------------
__device__ __forceinline__ uint32_t smem_u32(const void* p) {
    uint32_t a;
    asm("{ .reg .u64 t; cvta.to.shared.u64 t, %1; cvt.u32.u64 %0, t; }" : "=r"(a) : "l"(p));
    return a;
}
__device__ __forceinline__ void cpa16(uint32_t dst, const void* src) {
    asm volatile("cp.async.cg.shared.global [%0], [%1], 16;" :: "r"(dst), "l"(src));
}
#define CPC() asm volatile("cp.async.commit_group;" ::: "memory")
#define CPW1() asm volatile("cp.async.wait_group 1;" ::: "memory")
__device__ __forceinline__ void ldsm4(uint32_t* r, uint32_t a) {
    asm volatile("ldmatrix.sync.aligned.m8n8.x4.shared.b16 {%0,%1,%2,%3}, [%4];"
                 : "=r"(r[0]), "=r"(r[1]), "=r"(r[2]), "=r"(r[3]) : "r"(a));
}
__device__ __forceinline__ void ldsm4t(uint32_t* r, uint32_t a) {
    asm volatile("ldmatrix.sync.aligned.m8n8.x4.trans.shared.b16 {%0,%1,%2,%3}, [%4];"
                 : "=r"(r[0]), "=r"(r[1]), "=r"(r[2]), "=r"(r[3]) : "r"(a));
}
__device__ __forceinline__ void mma16816(float* c, const uint32_t* a, const uint32_t* b) {
    asm volatile("mma.sync.aligned.m16n8k16.row.col.f32.f16.f16.f32 "
                 "{%0,%1,%2,%3},{%4,%5,%6,%7},{%8,%9},{%0,%1,%2,%3};"
                 : "+f"(c[0]), "+f"(c[1]), "+f"(c[2]), "+f"(c[3])
                 : "r"(a[0]), "r"(a[1]), "r"(a[2]), "r"(a[3]), "r"(b[0]), "r"(b[1]));
}
__device__ __forceinline__ uint32_t packh2(__half a, __half b) {
    __half2 t = __halves2half2(a, b);
    return *reinterpret_cast<uint32_t*>(&t);
}
__device__ __forceinline__ void lds128(float4& f, uint32_t a) {
    asm volatile("ld.shared.v4.f32 {%0,%1,%2,%3}, [%4];"
                 : "=f"(f.x), "=f"(f.y), "=f"(f.z), "=f"(f.w) : "r"(a));
}
__device__ __forceinline__ void sts64(uint32_t a, uint32_t v0, uint32_t v1) {
    asm volatile("st.shared.v2.u32 [%0], {%1,%2};" :: "r"(a), "r"(v0), "r"(v1) : "memory");
}
__device__ __forceinline__ void cvt_hilo(uint32_t hiA, uint32_t loA, float4 f) {
    __half hx = __float2half_rn(f.x), hy = __float2half_rn(f.y);
    __half hz = __float2half_rn(f.z), hw = __float2half_rn(f.w);
    __half lx = __float2half_rn(f.x - __half2float(hx));
    __half ly = __float2half_rn(f.y - __half2float(hy));
    __half lz = __float2half_rn(f.z - __half2float(hz));
    __half lw = __float2half_rn(f.w - __half2float(hw));
    sts64(hiA, packh2(hx, hy), packh2(hz, hw));
    sts64(loA, packh2(lx, ly), packh2(lz, lw));
}

// ---------------- shared warp compute: one 32-K chunk, 3-term split ----------------
__device__ __forceinline__ void compute_chunk(uint32_t aHi, uint32_t aLo,
                                              uint32_t bHi, uint32_t bLo,
                                              int lane, int wm, int wn,
                                              float acc[4][4][4]) {
    const int arow = lane & 15, aoff = (lane >> 4) * 16;
    const int brow = (lane & 7) + ((lane >> 3) & 1) * 8, boff = (lane >> 4) * 16;
#pragma unroll
    for (int k16 = 0; k16 < 2; k16++) {
        uint32_t bh[2][4], bl[2][4];
#pragma unroll
        for (int nj = 0; nj < 2; nj++) {
            ldsm4t(bh[nj], bHi + (k16 * 16 + brow) * 272 + (wn + nj * 16) * 2 + boff);
            ldsm4t(bl[nj], bLo + (k16 * 16 + brow) * 272 + (wn + nj * 16) * 2 + boff);
        }
#pragma unroll
        for (int mi = 0; mi < 4; mi++) {
            uint32_t ah[4], al[4];
            ldsm4(ah, aHi + (wm + 16 * mi + arow) * 80 + k16 * 32 + aoff);
            ldsm4(al, aLo + (wm + 16 * mi + arow) * 80 + k16 * 32 + aoff);
#pragma unroll
            for (int n8 = 0; n8 < 4; n8++)
                mma16816(acc[mi][n8], ah, &bh[n8 >> 1][(n8 & 1) * 2]);
#pragma unroll
            for (int n8 = 0; n8 < 4; n8++)
                mma16816(acc[mi][n8], ah, &bl[n8 >> 1][(n8 & 1) * 2]);
#pragma unroll
            for (int n8 = 0; n8 < 4; n8++)
                mma16816(acc[mi][n8], al, &bh[n8 >> 1][(n8 & 1) * 2]);
        }
    }
}

// ===========================================================================
// GEMM1: split-K partials of G = E @ H; A operand (E fp32) converted in-kernel.
// smem: staging 128x144B | Asplit 2hl x 10240 | Bsplit 2buf x 2hl x 8704
// ===========================================================================
#define M1_STG 0
#define M1_A0  18432
#define M1_B0  38912
#define GSMEM1 73728

__global__ __launch_bounds__(256, 2) void k_mm1(const float* __restrict__ E) {
    extern __shared__ char smem[];
    const uint32_t sb = smem_u32(smem);
    const int mt = blockIdx.x >> 1, nt = blockIdx.x & 1;
    const int s = blockIdx.y, b = blockIdx.z;
    const int tid = threadIdx.x, lane = tid & 31, w = tid >> 5;
    const int wm = (w & 1) * 64, wn = (w >> 1) * 32;
    const float* Af = E + ((size_t)b * ENSN + mt * 128) * XDIM + (size_t)s * 1024;
    const __half* Bh = g_Hhi + (size_t)(s * 1024) * 256 + nt * 128;
    const __half* Bl = g_Hlo + (size_t)(s * 1024) * 256 + nt * 128;

    float acc[4][4][4];
#pragma unroll
    for (int i = 0; i < 4; i++)
#pragma unroll
        for (int j = 0; j < 4; j++)
#pragma unroll
            for (int q = 0; q < 4; q++) acc[i][j][q] = 0.0f;

    auto issA = [&](int kbase) {
#pragma unroll
        for (int it = 0; it < 4; it++) {
            const int i = tid + it * 256;
            const int r = i >> 3, seg = i & 7;
            cpa16(sb + M1_STG + r * 144 + seg * 16, Af + (size_t)r * XDIM + kbase + seg * 4);
        }
    };
    auto issB = [&](int buf, int kbase) {
#pragma unroll
        for (int hl = 0; hl < 2; hl++) {
            const __half* src = hl ? Bl : Bh;
#pragma unroll
            for (int it = 0; it < 2; it++) {
                const int i = tid + it * 256;
                const int r = i >> 4, seg = i & 15;
                cpa16(sb + M1_B0 + buf * 17408 + hl * 8704 + r * 272 + seg * 16,
                      src + (size_t)(kbase + r) * 256 + seg * 8);
            }
        }
    };

    issA(0); issB(0, 0); CPC();
    issB(1, 32); CPC();

    const int r2 = tid >> 1, h2 = tid & 1;
    for (int c = 0; c < 32; c++) {
        CPW1();
        __syncthreads();
#pragma unroll
        for (int q = 0; q < 4; q++) {
            float4 f;
            lds128(f, sb + M1_STG + r2 * 144 + h2 * 64 + q * 16);
            cvt_hilo(sb + M1_A0 + r2 * 80 + h2 * 32 + q * 8,
                     sb + M1_A0 + 10240 + r2 * 80 + h2 * 32 + q * 8, f);
        }
        __syncthreads();
        if (c + 1 < 32) issA((c + 1) * 32);
        CPC();
        compute_chunk(sb + M1_A0, sb + M1_A0 + 10240,
                      sb + M1_B0 + (c & 1) * 17408, sb + M1_B0 + (c & 1) * 17408 + 8704,
                      lane, wm, wn, acc);
        __syncthreads();
        if (c + 2 < 32) issB(c & 1, (c + 2) * 32);
        CPC();
    }

    float* Cp = g_part + (size_t)(s * BATCH + b) * NSQ + (mt * 128) * 256 + nt * 128;
#pragma unroll
    for (int mi = 0; mi < 4; mi++)
#pragma unroll
        for (int n8 = 0; n8 < 4; n8++) {
            const int r = wm + 16 * mi + (lane >> 2);
            const int cc = wn + n8 * 8 + (lane & 3) * 2;
            *(float2*)(Cp + r * 256 + cc) = make_float2(acc[mi][n8][0], acc[mi][n8][1]);
            *(float2*)(Cp + (r + 8) * 256 + cc) = make_float2(acc[mi][n8][2], acc[mi][n8][3]);
        }
}

// ===========================================================================
// GEMM3: out = W' @ E; B operand (E fp32) staged DOUBLE-buffered 2-ahead,
// converted in-kernel. smem: stage 2x17408 | A 2buf x 2hl x 10240 | Bcvt 2hl x 8704
// ===========================================================================
#define M3_STG 0
#define M3_A0  34816
#define M3_B0  75776
#define GSMEM3 93184

__global__ __launch_bounds__(256, 2) void k_mm3(const float* __restrict__ E,
                                                float* __restrict__ out) {
    extern __shared__ char smem[];
    const uint32_t sb = smem_u32(smem);
    const int nt = blockIdx.x, mt = blockIdx.y, b = blockIdx.z;
    const int n0 = nt * 128;
    const int tid = threadIdx.x, lane = tid & 31, w = tid >> 5;
    const int wm = (w & 1) * 64, wn = (w >> 1) * 32;
    const float* Bf = E + (size_t)b * ENSN * XDIM + n0;
    const __half* Ah = g_Whi + (size_t)b * NSQ + (size_t)(mt * 128) * 256;
    const __half* Al = g_Wlo + (size_t)b * NSQ + (size_t)(mt * 128) * 256;

    float acc[4][4][4];
#pragma unroll
    for (int i = 0; i < 4; i++)
#pragma unroll
        for (int j = 0; j < 4; j++)
#pragma unroll
            for (int q = 0; q < 4; q++) acc[i][j][q] = 0.0f;

    auto issB = [&](int buf, int kbase) {
#pragma unroll
        for (int it = 0; it < 4; it++) {
            const int i = tid + it * 256;
            const int k = i >> 5, seg = i & 31;
            cpa16(sb + M3_STG + buf * 17408 + k * 544 + seg * 16,
                  Bf + (size_t)(kbase + k) * XDIM + seg * 4);
        }
    };
    auto issA = [&](int buf, int kbase) {
#pragma unroll
        for (int hl = 0; hl < 2; hl++) {
            const __half* src = hl ? Al : Ah;
#pragma unroll
            for (int it = 0; it < 2; it++) {
                const int i = tid + it * 256;
                const int r = i >> 2, seg = i & 3;
                cpa16(sb + M3_A0 + buf * 20480 + hl * 10240 + r * 80 + seg * 16,
                      src + (size_t)r * 256 + kbase + seg * 8);
            }
        }
    };

    issB(0, 0); issA(0, 0); CPC();      // group for chunk 0
    issB(1, 32); issA(1, 32); CPC();    // group for chunk 1

    const int k8 = tid >> 3, s8 = tid & 7;
    for (int c = 0; c < 8; c++) {
        CPW1();                          // group(c) complete
        __syncthreads();
        // convert stage[c&1] -> Bcvt (single buffer; prev compute done)
#pragma unroll
        for (int q = 0; q < 4; q++) {
            float4 f;
            lds128(f, sb + M3_STG + (c & 1) * 17408 + k8 * 544 + s8 * 64 + q * 16);
            cvt_hilo(sb + M3_B0 + k8 * 272 + s8 * 32 + q * 8,
                     sb + M3_B0 + 8704 + k8 * 272 + s8 * 32 + q * 8, f);
        }
        __syncthreads();
        compute_chunk(sb + M3_A0 + (c & 1) * 20480, sb + M3_A0 + (c & 1) * 20480 + 10240,
                      sb + M3_B0, sb + M3_B0 + 8704,
                      lane, wm, wn, acc);
        __syncthreads();
        if (c + 2 < 8) { issB(c & 1, (c + 2) * 32); issA(c & 1, (c + 2) * 32); }
        CPC();
    }

    float* Op = out + (size_t)b * ENSN * XDIM;
#pragma unroll
    for (int mi = 0; mi < 4; mi++)
#pragma unroll
        for (int n8 = 0; n8 < 4; n8++) {
            const int e = mt * 128 + wm + 16 * mi + (lane >> 2);
            const int x = n0 + wn + n8 * 8 + (lane & 3) * 2;
            *(float2*)(Op + (size_t)e * XDIM + x) =
                make_float2(acc[mi][n8][0], acc[mi][n8][1]);
            *(float2*)(Op + (size_t)(e + 8) * XDIM + x) =
                make_float2(acc[mi][n8][2], acc[mi][n8][3]);
        }
}

// ---------------------------------------------------------------------------
__global__ void k_dummy() {
    const int i = threadIdx.x;
#pragma unroll
    for (int r = 0; r < 8; r++) g_mu[r * 256 + i] = 0.0f;
}

__global__ __launch_bounds__(256) void k_splitH(const float* __restrict__ H) {
    const size_t i = (size_t)blockIdx.x * 256 + threadIdx.x;
    float4 v = ((const float4*)H)[i];
    __half hx = __float2half_rn(v.x), hy = __float2half_rn(v.y);
    __half hz = __float2half_rn(v.z), hw = __float2half_rn(v.w);
    __half2* hi = (__half2*)g_Hhi;
    __half2* lo = (__half2*)g_Hlo;
    hi[2 * i]     = __halves2half2(hx, hy);
    hi[2 * i + 1] = __halves2half2(hz, hw);
    lo[2 * i]     = __halves2half2(__float2half_rn(v.x - __half2float(hx)),
                                   __float2half_rn(v.y - __half2float(hy)));
    lo[2 * i + 1] = __halves2half2(__float2half_rn(v.z - __half2float(hz)),
                                   __float2half_rn(v.w - __half2float(hw)));
}

__global__ __launch_bounds__(256) void k_reduce() {
    const int i = blockIdx.x * 256 + threadIdx.x;
    const float4* P = (const float4*)g_part;
    float4 s = P[i];
#pragma unroll
    for (int p = 1; p < SPLITS; p++) {
        float4 v = P[(size_t)p * (BATCH * NSQ / 4) + i];
        s.x += v.x; s.y += v.y; s.z += v.z; s.w += v.w;
    }
    ((float4*)g_G)[i] = s;
}

__global__ __launch_bounds__(256) void k_colmean() {
    const int b = blockIdx.y;
    const int j = blockIdx.x * 32 + (threadIdx.x & 31);
    const int er = threadIdx.x >> 5;
    const float* G = g_G + b * NSQ;
    float s = 0.0f;
    for (int e = er; e < ENSN; e += 8) s += G[e * 256 + j];
    __shared__ float red[8][32];
    red[er][threadIdx.x & 31] = s;
    __syncthreads();
    if (er == 0) {
        float t = 0.0f;
#pragma unroll
        for (int r = 0; r < 8; r++) t += red[r][threadIdx.x & 31];
        g_mu[b * 256 + j] = t * (1.0f / 256.0f);
    }
}

__global__ __launch_bounds__(256) void k_centerT(const float* __restrict__ ymean,
                                                 const float* __restrict__ ystd,
                                                 const float* __restrict__ noise) {
    const int b = blockIdx.z, j0 = blockIdx.y * 32, e0 = blockIdx.x * 32;
    float* G = g_G + b * NSQ;
    float* Z = g_Z + b * NSQ;
    const float* nz = noise + b * NSQ;
    __shared__ float T[32][33];
    const int tx = threadIdx.x & 31, ty = threadIdx.x >> 5;
    const float mu = g_mu[b * 256 + j0 + tx];
#pragma unroll
    for (int r = 0; r < 4; r++) {
        const int e = e0 + ty + r * 8;
        float gc = G[e * 256 + j0 + tx] - mu;
        G[e * 256 + j0 + tx] = gc;
        T[ty + r * 8][tx] = gc;
    }
    __syncthreads();
#pragma unroll
    for (int r = 0; r < 4; r++) {
        const int j = j0 + ty + r * 8;
        const float ym = ymean[j];
        const float sd = ystd[j];
        Z[j * 256 + e0 + tx] = ym - T[tx][ty + r * 8] + nz[j * 256 + e0 + tx] * sd * sd;
    }
}

__global__ __launch_bounds__(256) void k_cyy(const float* __restrict__ ystd) {
    const int b = blockIdx.y;
    const int u0 = (blockIdx.x >> 2) * 64, v0 = (blockIdx.x & 3) * 64;
    const float* G = g_G + b * NSQ;
    float* A = g_A + b * NSQ;
    __shared__ float Us[16][64];
    __shared__ float Vs[16][64];
    const int tx = threadIdx.x & 15, ty = threadIdx.x >> 4;
    const int lk = threadIdx.x >> 4, lc = (threadIdx.x & 15) * 4;
    float acc[4][4];
#pragma unroll
    for (int i = 0; i < 4; i++)
#pragma unroll
        for (int j = 0; j < 4; j++) acc[i][j] = 0.0f;

    for (int ee = 0; ee < 256; ee += 16) {
        *(float4*)&Us[lk][lc] = *(const float4*)&G[(ee + lk) * 256 + u0 + lc];
        *(float4*)&Vs[lk][lc] = *(const float4*)&G[(ee + lk) * 256 + v0 + lc];
        __syncthreads();
#pragma unroll
        for (int k = 0; k < 16; k++) {
            float4 u = *(float4*)&Us[k][ty * 4];
            float4 v = *(float4*)&Vs[k][tx * 4];
            float ua[4] = {u.x, u.y, u.z, u.w};
            float va[4] = {v.x, v.y, v.z, v.w};
#pragma unroll
            for (int i = 0; i < 4; i++)
#pragma unroll
                for (int j = 0; j < 4; j++) acc[i][j] = fmaf(ua[i], va[j], acc[i][j]);
        }
        __syncthreads();
    }
#pragma unroll
    for (int i = 0; i < 4; i++)
#pragma unroll
        for (int j = 0; j < 4; j++) {
            const int u = u0 + ty * 4 + i, v = v0 + tx * 4 + j;
            float val = acc[i][j] * (1.0f / 256.0f);
            if (u == v) { float sd = ystd[u]; val += sd * sd; }
            A[u * 256 + v] = val;
        }
}

// ---------------------------------------------------------------------------
// Blocked Cholesky (r12): parallel pivots, 4x4 reg-tiled trailing update
// ---------------------------------------------------------------------------
__global__ __launch_bounds__(256) void k_chol() {
    const int b = blockIdx.x;
    float* a = g_A + b * NSQ;
    __shared__ float P[256][33];
    __shared__ float sD[32];
    const int tid = threadIdx.x;

    for (int kb = 0; kb < 8; kb++) {
        const int j0 = kb * 32;
        if (tid >= j0) {
#pragma unroll
            for (int c = 0; c < 32; c++) P[tid][c] = a[tid * 256 + j0 + c];
        }
        __syncthreads();
        for (int k = 0; k < 32; k++) {
            const int gk = j0 + k;
            const float piv = P[gk][k];
            const float d = sqrtf(piv);
            const float rd = 1.0f / d;
            if (tid == gk) sD[k] = d;
            if (tid > gk) P[tid][k] *= rd;
            __syncthreads();
            if (tid > gk) {
                const float lrk = P[tid][k];
#pragma unroll
                for (int c = k + 1; c < 32; c++) P[tid][c] -= lrk * P[j0 + c][k];
            }
            __syncthreads();
        }
        if (tid >= j0) {
#pragma unroll
            for (int c = 0; c < 32; c++) {
                float val = P[tid][c];
                if (tid - j0 == c) val = sD[c];
                a[tid * 256 + j0 + c] = val;
            }
        }
        __syncthreads();
        const int rem = 224 - j0;
        if (rem > 0) {
            const int nt4 = rem >> 2;
            for (int t = tid; t < nt4 * nt4; t += 256) {
                const int ti = t / nt4, tj = t - ti * nt4;
                const int r0 = j0 + 32 + ti * 4, c0 = j0 + 32 + tj * 4;
                float4 acc[4];
#pragma unroll
                for (int i = 0; i < 4; i++)
                    acc[i] = *(float4*)&a[(r0 + i) * 256 + c0];
#pragma unroll
                for (int k = 0; k < 32; k++) {
                    float pr[4], pc[4];
#pragma unroll
                    for (int i = 0; i < 4; i++) { pr[i] = P[r0 + i][k]; pc[i] = P[c0 + i][k]; }
#pragma unroll
                    for (int i = 0; i < 4; i++) {
                        acc[i].x = fmaf(-pr[i], pc[0], acc[i].x);
                        acc[i].y = fmaf(-pr[i], pc[1], acc[i].y);
                        acc[i].z = fmaf(-pr[i], pc[2], acc[i].z);
                        acc[i].w = fmaf(-pr[i], pc[3], acc[i].w);
                    }
                }
#pragma unroll
                for (int i = 0; i < 4; i++)
                    *(float4*)&a[(r0 + i) * 256 + c0] = acc[i];
            }
        }
        __syncthreads();
    }
}

__global__ void k_invdiag() {
    const int p = blockIdx.x & 7, b = blockIdx.x >> 3, j0 = p * 32;
    const float* a = g_A + b * NSQ;
    __shared__ float Ld[32][33];
    __shared__ float Xc[32][33];
    const int lane = threadIdx.x;
    for (int i = 0; i < 32; i++) Ld[i][lane] = a[(j0 + i) * 256 + j0 + lane];
    __syncwarp();
    for (int i = 0; i < 32; i++) {
        float s = (i == lane) ? 1.0f : 0.0f;
        for (int k = lane; k < i; k++) s -= Ld[i][k] * Xc[k][lane];
        Xc[i][lane] = (i >= lane) ? s / Ld[i][i] : 0.0f;
    }
    __syncwarp();
    for (int i = 0; i < 32; i++)
        g_Dinv[(b * 8 + p) * 1024 + i * 32 + lane] = Xc[i][lane];
}

// ---------------------------------------------------------------------------
// Trisolve, register-cached Z panel
// ---------------------------------------------------------------------------
#define TS_SMEM 129920
__global__ __launch_bounds__(256) void k_trisolve2() {
    extern __shared__ float sm[];
    float (*Zs)[65] = (float(*)[65])sm;
    float (*Dv)[33] = (float(*)[33])(sm + 256 * 65);
    float (*Lp)[33] = (float(*)[33])(sm + 256 * 65 + 256 * 33);
    const int b = blockIdx.y, e0 = blockIdx.x * 64;
    const float* L = g_A + b * NSQ;
    float* Z = g_Z + b * NSQ;
    const int tid = threadIdx.x, c = tid & 63, rg = tid >> 6;

    for (int idx = tid; idx < 256 * 64; idx += 256)
        Zs[idx >> 6][idx & 63] = Z[(idx >> 6) * 256 + e0 + (idx & 63)];
    for (int idx = tid; idx < 8 * 32 * 32; idx += 256)
        Dv[idx >> 5][idx & 31] = g_Dinv[b * 8192 + idx];
    __syncthreads();

    for (int p = 0; p < 8; p++) {
        const int j0 = p * 32, rem = 224 - j0;
        float zr[32];
#pragma unroll
        for (int k = 0; k < 32; k++) zr[k] = Zs[j0 + k][c];
        float w[8];
#pragma unroll
        for (int q = 0; q < 8; q++) {
            const int r = rg * 8 + q;
            float s = 0.0f;
#pragma unroll
            for (int k = 0; k < 32; k++) s = fmaf(Dv[p * 32 + r][k], zr[k], s);
            w[q] = s;
        }
        for (int idx = tid; idx < rem * 32; idx += 256)
            Lp[idx >> 5][idx & 31] = L[(j0 + 32 + (idx >> 5)) * 256 + j0 + (idx & 31)];
        __syncthreads();
#pragma unroll
        for (int q = 0; q < 8; q++) Zs[j0 + rg * 8 + q][c] = w[q];
        __syncthreads();
#pragma unroll
        for (int k = 0; k < 32; k++) zr[k] = Zs[j0 + k][c];
        for (int rr = rg; rr < rem; rr += 4) {
            float acc = Zs[j0 + 32 + rr][c];
#pragma unroll
            for (int k = 0; k < 32; k++) acc = fmaf(-Lp[rr][k], zr[k], acc);
            Zs[j0 + 32 + rr][c] = acc;
        }
        __syncthreads();
    }

    for (int p = 7; p >= 0; p--) {
        const int j0 = p * 32;
        float zr[32];
#pragma unroll
        for (int i = 0; i < 32; i++) zr[i] = Zs[j0 + i][c];
        float w[8];
#pragma unroll
        for (int q = 0; q < 8; q++) {
            const int k = rg * 8 + q;
            float s = 0.0f;
#pragma unroll
            for (int i = 0; i < 32; i++) s = fmaf(Dv[p * 32 + i][k], zr[i], s);
            w[q] = s;
        }
        for (int idx = tid; idx < j0 * 32; idx += 256)
            Lp[idx >> 5][idx & 31] = L[(j0 + (idx & 31)) * 256 + (idx >> 5)];
        __syncthreads();
#pragma unroll
        for (int q = 0; q < 8; q++) Zs[j0 + rg * 8 + q][c] = w[q];
        __syncthreads();
#pragma unroll
        for (int k = 0; k < 32; k++) zr[k] = Zs[j0 + k][c];
        for (int t = rg; t < j0; t += 4) {
            float acc = Zs[t][c];
#pragma unroll
            for (int k = 0; k < 32; k++) acc = fmaf(-Lp[t][k], zr[k], acc);
            Zs[t][c] = acc;
        }
        __syncthreads();
    }

    for (int idx = tid; idx < 256 * 64; idx += 256)
        Z[(idx >> 6) * 256 + e0 + (idx & 63)] = Zs[idx >> 6][idx & 63];
}

// W'[e][f] = (e==f) + (1/ens) sum_j Z[j][e] * Gc[f][j]  -> fp16 hi/lo
__global__ __launch_bounds__(256) void k_wp() {
    const int b = blockIdx.y;
    const int e0 = (blockIdx.x >> 2) * 64, f0 = (blockIdx.x & 3) * 64;
    const float* G = g_G + b * NSQ;
    const float* Z = g_Z + b * NSQ;
    __shared__ float sZ[16][64];
    __shared__ float sG[16][64];
    const int tx = threadIdx.x & 15, ty = threadIdx.x >> 4;
    const int lk = threadIdx.x >> 4, lc = (threadIdx.x & 15) * 4;
    const int gn = threadIdx.x >> 2, gk = (threadIdx.x & 3) * 4;
    float acc[4][4];
#pragma unroll
    for (int i = 0; i < 4; i++)
#pragma unroll
        for (int j = 0; j < 4; j++) acc[i][j] = 0.0f;

    for (int jj = 0; jj < 256; jj += 16) {
        *(float4*)&sZ[lk][lc] = *(const float4*)&Z[(jj + lk) * 256 + e0 + lc];
        float4 gv = *(const float4*)&G[(f0 + gn) * 256 + jj + gk];
        sG[gk + 0][gn] = gv.x; sG[gk + 1][gn] = gv.y;
        sG[gk + 2][gn] = gv.z; sG[gk + 3][gn] = gv.w;
        __syncthreads();
#pragma unroll
        for (int k = 0; k < 16; k++) {
            float4 zv = *(float4*)&sZ[k][ty * 4];
            float4 gg = *(float4*)&sG[k][tx * 4];
            float za[4] = {zv.x, zv.y, zv.z, zv.w};
            float ga[4] = {gg.x, gg.y, gg.z, gg.w};
#pragma unroll
            for (int i = 0; i < 4; i++)
#pragma unroll
                for (int j = 0; j < 4; j++) acc[i][j] = fmaf(za[i], ga[j], acc[i][j]);
        }
        __syncthreads();
    }
#pragma unroll
    for (int i = 0; i < 4; i++)
#pragma unroll
        for (int j = 0; j < 4; j++) {
            const int e = e0 + ty * 4 + i, f = f0 + tx * 4 + j;
            float val = acc[i][j] * (1.0f / 256.0f);
            if (e == f) val += 1.0f;
            __half h = __float2half_rn(val);
            g_Whi[b * NSQ + e * 256 + f] = h;
            g_Wlo[b * NSQ + e * 256 + f] = __float2half_rn(val - __half2float(h));
        }
}

// ---------------------------------------------------------------------------
extern "C" void kernel_launch(void* const* d_in, const int* in_sizes, int n_in,
                              void* d_out, int out_size) {
    const float* E     = (const float*)d_in[0];
    const float* H     = (const float*)d_in[1];
    const float* ymean = (const float*)d_in[2];
    const float* ystd  = (const float*)d_in[3];
    const float* noise = (const float*)d_in[4];
    float* out = (float*)d_out;

    cudaFuncSetAttribute(k_mm1, cudaFuncAttributeMaxDynamicSharedMemorySize, GSMEM1);
    cudaFuncSetAttribute(k_mm3, cudaFuncAttributeMaxDynamicSharedMemorySize, GSMEM3);
    cudaFuncSetAttribute(k_trisolve2, cudaFuncAttributeMaxDynamicSharedMemorySize, TS_SMEM);

    k_dummy<<<1, 256>>>();                                  // idx 0
    k_splitH<<<2048, 256>>>(H);                             // idx 1
    k_dummy<<<1, 256>>>();                                  // idx 2
    k_mm1<<<dim3(4, SPLITS, BATCH), 256, GSMEM1>>>(E);      // idx 3  <- ncu capture
    k_reduce<<<(BATCH * NSQ / 4) / 256, 256>>>();
    k_colmean<<<dim3(8, BATCH), 256>>>();
    k_centerT<<<dim3(8, 8, BATCH), 256>>>(ymean, ystd, noise);
    k_cyy<<<dim3(16, BATCH), 256>>>(ystd);
    k_chol<<<BATCH, 256>>>();
    k_invdiag<<<64, 32>>>();
    k_trisolve2<<<dim3(4, BATCH), 256, TS_SMEM>>>();
    k_wp<<<dim3(16, BATCH), 256>>>();
    k_mm3<<<dim3(64, 2, BATCH), 256, GSMEM3>>>(E, out);
}